// round 8
// baseline (speedup 1.0000x reference)
#include <cuda_runtime.h>
#include <cstdint>

// Problem constants
#define BB   64      // batch
#define TT   1024    // time steps
#define HH   256     // hidden per direction
#define DIN  136     // input features (68*2)
#define G4   1024    // 4*H
#define CL   8       // cluster size
#define BPC  8       // batches per cluster
#define JPC  32      // hidden units per CTA

// ---------------- scratch (device globals; no allocations allowed) ----------------
__device__ __align__(16) float g_proj[2][(size_t)TT * G4 * BB]; // [dir][t][row][b]
__device__ __align__(16) float g_hs[(size_t)TT * 2 * HH * BB];  // [t][dir*H+j][b]

// ---------------- activations ----------------
__device__ __forceinline__ float sigf(float x) {
    return 1.0f / (1.0f + __expf(-x));
}
__device__ __forceinline__ float tanh_fast(float x) {
    float xx = fminf(fmaxf(x, -10.0f), 10.0f);
    float e = __expf(2.0f * xx);
    return (e - 1.0f) / (e + 1.0f);
}

// ---------------- DSMEM scalar store to peer rank (same SMEM offset) --------------
__device__ __forceinline__ void st_cluster_f32(uint32_t laddr, uint32_t rank, float v) {
    asm volatile(
        "{\n\t"
        ".reg .b32 r;\n\t"
        "mapa.shared::cluster.u32 r, %0, %1;\n\t"
        "st.shared::cluster.f32 [r], %2;\n\t"
        "}"
        :: "r"(laddr), "r"(rank), "f"(v) : "memory");
}

// ---------------- input projection GEMM (R1 math; occupancy 3) --------------------
__global__ void __launch_bounds__(128, 3) proj_kernel(
    const float* __restrict__ x,
    const float* __restrict__ wih_f, const float* __restrict__ wih_b,
    const float* __restrict__ bih_f, const float* __restrict__ bih_b)
{
    extern __shared__ float sm[];
    float* xs = sm;               // [136][68] transposed: xs[k][b]
    float* ws = sm + 136 * 68;    // [136][68] transposed: ws[k][r]

    const int t   = blockIdx.y;
    const int dir = blockIdx.z;
    const int r0  = blockIdx.x * 64;
    const float* w  = dir ? wih_b : wih_f;
    const float* bi = dir ? bih_b : bih_f;
    const int tid = threadIdx.x;

    for (int i = tid; i < 64 * 34; i += 128) {
        int b = i / 34, k4 = i - b * 34;
        float4 v = __ldg(((const float4*)(x + ((size_t)b * TT + t) * DIN)) + k4);
        int kb = k4 * 4;
        xs[(kb + 0) * 68 + b] = v.x;
        xs[(kb + 1) * 68 + b] = v.y;
        xs[(kb + 2) * 68 + b] = v.z;
        xs[(kb + 3) * 68 + b] = v.w;
    }
    for (int i = tid; i < 64 * 34; i += 128) {
        int r = i / 34, k4 = i - r * 34;
        float4 v = __ldg(((const float4*)(w + (size_t)(r0 + r) * DIN)) + k4);
        int kb = k4 * 4;
        ws[(kb + 0) * 68 + r] = v.x;
        ws[(kb + 1) * 68 + r] = v.y;
        ws[(kb + 2) * 68 + r] = v.z;
        ws[(kb + 3) * 68 + r] = v.w;
    }
    __syncthreads();

    const int tx = tid & 15;
    const int ty = tid >> 4;
    float acc[8][4];
#pragma unroll
    for (int q = 0; q < 8; q++)
#pragma unroll
        for (int j = 0; j < 4; j++) acc[q][j] = 0.0f;

#pragma unroll 4
    for (int k = 0; k < DIN; k++) {
        float4 xv = *(const float4*)(xs + k * 68 + tx * 4);
        float4 w0 = *(const float4*)(ws + k * 68 + ty * 8);
        float4 w1 = *(const float4*)(ws + k * 68 + ty * 8 + 4);
        float wv[8] = {w0.x, w0.y, w0.z, w0.w, w1.x, w1.y, w1.z, w1.w};
#pragma unroll
        for (int q = 0; q < 8; q++) {
            acc[q][0] += wv[q] * xv.x;
            acc[q][1] += wv[q] * xv.y;
            acc[q][2] += wv[q] * xv.z;
            acc[q][3] += wv[q] * xv.w;
        }
    }

    float* dst = g_proj[dir] + (size_t)t * G4 * BB;
#pragma unroll
    for (int q = 0; q < 8; q++) {
        int row = r0 + ty * 8 + q;
        float bias = __ldg(bi + row);
        float4 o = make_float4(acc[q][0] + bias, acc[q][1] + bias,
                               acc[q][2] + bias, acc[q][3] + bias);
        *(float4*)(dst + (size_t)row * BB + tx * 4) = o;
    }
}

// ---------------- clustered recurrent scan (no split-k) ----------------
// 128 CTAs = 16 clusters of 8. Cluster = (dir, 8-batch group). CTA owns 32 j.
// Warp owns 16 gate rows full-K; weights in padded SMEM (broadcast LDS).
// h double-buffered SMEM; direct DSMEM scatter; one cluster barrier per step.
__global__ void __launch_bounds__(256, 1) __cluster_dims__(CL, 1, 1)
scan_kernel(const float* __restrict__ whh_f, const float* __restrict__ whh_b,
            const float* __restrict__ bhh_f, const float* __restrict__ bhh_b)
{
    extern __shared__ float smem[];
    float* h_s = smem;                    // [2][256 k][8 b]    16384 B
    float* w_s = smem + 4096;             // [256 k][132 pad]  135168 B
    float* gsm = smem + 4096 + 33792;     // [128 rl][12 pad]    6144 B

    const int cid  = blockIdx.x >> 3;     // cluster 0..15
    const int rank = blockIdx.x & 7;
    const int dir  = cid >> 3;
    const int b0   = (cid & 7) * BPC;
    const int j0   = rank * JPC;
    const float* whh = dir ? whh_b : whh_f;
    const float* bhh = dir ? bhh_b : bhh_f;
    const int tid  = threadIdx.x;
    const int lane = tid & 31;
    const int w    = tid >> 5;

    // weights into SMEM: w_s[k*132 + rl] = whh[(rl>>5)*256 + j0 + (rl&31)][k]
    for (int idx = tid; idx < 128 * 64; idx += 256) {
        int rl = idx >> 6, k4 = idx & 63;
        int grow = (rl >> 5) * 256 + j0 + (rl & 31);
        float4 v = __ldg((const float4*)(whh + (size_t)grow * HH) + k4);
        w_s[(k4 * 4 + 0) * 132 + rl] = v.x;
        w_s[(k4 * 4 + 1) * 132 + rl] = v.y;
        w_s[(k4 * 4 + 2) * 132 + rl] = v.z;
        w_s[(k4 * 4 + 3) * 132 + rl] = v.w;
    }
    // zero h buffer 0
    for (int i = tid; i < 2048; i += 256) h_s[i] = 0.0f;

    // state-phase mapping: thread owns (jj, b); (jj*8+b) == tid
    const int jj = tid >> 3;
    const int b  = tid & 7;
    float bh[4];
#pragma unroll
    for (int g = 0; g < 4; g++) bh[g] = __ldg(bhh + g * 256 + j0 + jj);

    // GEMM mapping: warp w -> rows w*16..+15; lane -> (row, batch-half)
    const int rl  = w * 16 + (lane >> 1);   // local gate row 0..127
    const int bh4 = (lane & 1) * 4;         // batch offset 0 or 4
    const float* wcol = w_s + rl;

    __syncthreads();
    asm volatile("barrier.cluster.arrive.aligned;" ::: "memory");
    asm volatile("barrier.cluster.wait.aligned;" ::: "memory");

    float c = 0.0f;

    for (int s = 0; s < TT; ++s) {
        const int t = dir ? (TT - 1 - s) : s;
        const int p = s & 1;

        // prefetch x-projection gate values (consumed after GEMM)
        float pf[4];
#pragma unroll
        for (int g = 0; g < 4; g++)
            pf[g] = __ldg(g_proj[dir] + ((size_t)t * G4 + g * 256 + j0 + jj) * BB + b0 + b);

        // full-K GEMM: 1 row x 4 batches per lane
        float a0 = 0.0f, a1 = 0.0f, a2 = 0.0f, a3 = 0.0f;
        const float* hp = h_s + p * 2048 + bh4;
#pragma unroll 8
        for (int k = 0; k < HH; k++) {
            float wv = wcol[k * 132];
            float4 hv = *(const float4*)(hp + k * 8);
            a0 += wv * hv.x; a1 += wv * hv.y;
            a2 += wv * hv.z; a3 += wv * hv.w;
        }
        *(float4*)(gsm + rl * 12 + bh4) = make_float4(a0, a1, a2, a3);
        __syncthreads();

        // cell: gather 4 gates for (jj, b)
        float gv[4];
#pragma unroll
        for (int g = 0; g < 4; g++)
            gv[g] = pf[g] + bh[g] + gsm[(g * 32 + jj) * 12 + b];
        float i_ = sigf(gv[0]);
        float f_ = sigf(gv[1]);
        float g_ = tanh_fast(gv[2]);
        float o_ = sigf(gv[3]);
        c = f_ * c + i_ * g_;
        float h = o_ * tanh_fast(c);

        // hidden sequence (global)
        g_hs[((size_t)t * 512 + dir * 256 + j0 + jj) * BB + b0 + b] = h;

        // publish h: local store + DSMEM scatter to 7 peers (same offset)
        {
            int off = (p ^ 1) * 2048 + j0 * 8 + tid;   // own slice contiguous
            h_s[off] = h;
            uint32_t laddr = (uint32_t)__cvta_generic_to_shared(h_s + off);
#pragma unroll
            for (int r = 1; r < CL; r++)
                st_cluster_f32(laddr, (uint32_t)((rank + r) & 7), h);
        }

        // cluster barrier: block-wide + cluster-wide sync, release/acquire,
        // orders DSMEM stores, guards exit on last step
        asm volatile("barrier.cluster.arrive.aligned;" ::: "memory");
        asm volatile("barrier.cluster.wait.aligned;" ::: "memory");
    }
}

// ---------------- final FC ----------------
__global__ void __launch_bounds__(320) fc_kernel(
    const float* __restrict__ fcw, const float* __restrict__ fcb,
    float* __restrict__ out)
{
    const int t = blockIdx.x;
    const int o = threadIdx.x / 64;  // 0..4
    const int b = threadIdx.x & 63;  // 0..63
    const float* hp = g_hs + (size_t)t * 512 * BB + b;
    const float* wp = fcw + o * 512;
    float acc = 0.0f;
#pragma unroll 8
    for (int j = 0; j < 512; j++)
        acc += hp[(size_t)j * BB] * __ldg(wp + j);
    out[((size_t)b * TT + t) * 5 + o] = acc + __ldg(fcb + o);
}

// ---------------- launch ----------------
extern "C" void kernel_launch(void* const* d_in, const int* in_sizes, int n_in,
                              void* d_out, int out_size)
{
    const float* x      = (const float*)d_in[0];
    const float* wih_f  = (const float*)d_in[1];
    const float* whh_f  = (const float*)d_in[2];
    const float* bih_f  = (const float*)d_in[3];
    const float* bhh_f  = (const float*)d_in[4];
    const float* wih_b  = (const float*)d_in[5];
    const float* whh_b  = (const float*)d_in[6];
    const float* bih_b  = (const float*)d_in[7];
    const float* bhh_b  = (const float*)d_in[8];
    const float* fcw    = (const float*)d_in[9];
    const float* fcb    = (const float*)d_in[10];
    float* out = (float*)d_out;

    const int proj_smem = 2 * 136 * 68 * (int)sizeof(float);          // 73,984 B
    const int scan_smem = (4096 + 33792 + 1536) * (int)sizeof(float); // 157,696 B
    cudaFuncSetAttribute(proj_kernel, cudaFuncAttributeMaxDynamicSharedMemorySize, proj_smem);
    cudaFuncSetAttribute(scan_kernel, cudaFuncAttributeMaxDynamicSharedMemorySize, scan_smem);

    dim3 pg(16, TT, 2);
    proj_kernel<<<pg, 128, proj_smem>>>(x, wih_f, wih_b, bih_f, bih_b);

    scan_kernel<<<128, 256, scan_smem>>>(whh_f, whh_b, bhh_f, bhh_b);

    fc_kernel<<<TT, 320>>>(fcw, fcb, out);
}

// round 10
// speedup vs baseline: 2.8592x; 2.8592x over previous
#include <cuda_runtime.h>
#include <cuda_bf16.h>
#include <cstdint>

// Problem constants
#define BB   64
#define TT   1024
#define HH   256
#define DIN  136
#define G4   1024
#define CL   8       // cluster size
#define BPC  8       // batches per cluster
#define JPC  32      // hidden units per CTA

// ---------------- scratch ----------------
__device__ __align__(16) float g_proj[2][(size_t)TT * G4 * BB]; // [dir][t][row][b]
__device__ __align__(16) float g_hs[(size_t)TT * 2 * HH * BB];  // [t][dir*H+j][b]

// ---------------- activations ----------------
__device__ __forceinline__ float sigf(float x) { return 1.0f / (1.0f + __expf(-x)); }
__device__ __forceinline__ float tanh_fast(float x) {
    float xx = fminf(fmaxf(x, -10.0f), 10.0f);
    float e = __expf(2.0f * xx);
    return (e - 1.0f) / (e + 1.0f);
}

// ---------------- DSMEM float4 store to peer rank ----------------
__device__ __forceinline__ void st_cluster_f4(uint32_t laddr, uint32_t rank, float4 v) {
    asm volatile(
        "{\n\t.reg .b32 r;\n\t"
        "mapa.shared::cluster.u32 r, %0, %1;\n\t"
        "st.shared::cluster.v4.f32 [r], {%2, %3, %4, %5};\n\t}"
        :: "r"(laddr), "r"(rank), "f"(v.x), "f"(v.y), "f"(v.z), "f"(v.w) : "memory");
}

// ---------------- warp-level bf16 MMA (baseline PTX, works on sm_103) -------------
__device__ __forceinline__ void mma16816(float* d, const uint32_t* a,
                                         uint32_t b0, uint32_t b1) {
    asm volatile(
        "mma.sync.aligned.m16n8k16.row.col.f32.bf16.bf16.f32 "
        "{%0,%1,%2,%3}, {%4,%5,%6,%7}, {%8,%9}, {%0,%1,%2,%3};"
        : "+f"(d[0]), "+f"(d[1]), "+f"(d[2]), "+f"(d[3])
        : "r"(a[0]), "r"(a[1]), "r"(a[2]), "r"(a[3]), "r"(b0), "r"(b1));
}
__device__ __forceinline__ uint32_t pack_bf16x2(float lo, float hi) {
    __nv_bfloat162 t = __floats2bfloat162_rn(lo, hi);   // x -> low bits
    return *(uint32_t*)&t;
}

// ---------------- input projection GEMM (R1/R6, known-good) ----------------
__global__ void __launch_bounds__(128, 2) proj_kernel(
    const float* __restrict__ x,
    const float* __restrict__ wih_f, const float* __restrict__ wih_b,
    const float* __restrict__ bih_f, const float* __restrict__ bih_b)
{
    extern __shared__ float sm[];
    float* xs = sm;
    float* ws = sm + 136 * 68;

    const int t   = blockIdx.y;
    const int dir = blockIdx.z;
    const int r0  = blockIdx.x * 64;
    const float* w  = dir ? wih_b : wih_f;
    const float* bi = dir ? bih_b : bih_f;
    const int tid = threadIdx.x;

    for (int i = tid; i < 64 * 34; i += 128) {
        int b = i / 34, k4 = i - b * 34;
        float4 v = __ldg(((const float4*)(x + ((size_t)b * TT + t) * DIN)) + k4);
        int kb = k4 * 4;
        xs[(kb + 0) * 68 + b] = v.x; xs[(kb + 1) * 68 + b] = v.y;
        xs[(kb + 2) * 68 + b] = v.z; xs[(kb + 3) * 68 + b] = v.w;
    }
    for (int i = tid; i < 64 * 34; i += 128) {
        int r = i / 34, k4 = i - r * 34;
        float4 v = __ldg(((const float4*)(w + (size_t)(r0 + r) * DIN)) + k4);
        int kb = k4 * 4;
        ws[(kb + 0) * 68 + r] = v.x; ws[(kb + 1) * 68 + r] = v.y;
        ws[(kb + 2) * 68 + r] = v.z; ws[(kb + 3) * 68 + r] = v.w;
    }
    __syncthreads();

    const int tx = tid & 15;
    const int ty = tid >> 4;
    float acc[8][4];
#pragma unroll
    for (int q = 0; q < 8; q++)
#pragma unroll
        for (int j = 0; j < 4; j++) acc[q][j] = 0.0f;

#pragma unroll 4
    for (int k = 0; k < DIN; k++) {
        float4 xv = *(const float4*)(xs + k * 68 + tx * 4);
        float4 w0 = *(const float4*)(ws + k * 68 + ty * 8);
        float4 w1 = *(const float4*)(ws + k * 68 + ty * 8 + 4);
        float wv[8] = {w0.x, w0.y, w0.z, w0.w, w1.x, w1.y, w1.z, w1.w};
#pragma unroll
        for (int q = 0; q < 8; q++) {
            acc[q][0] += wv[q] * xv.x; acc[q][1] += wv[q] * xv.y;
            acc[q][2] += wv[q] * xv.z; acc[q][3] += wv[q] * xv.w;
        }
    }

    float* dst = g_proj[dir] + (size_t)t * G4 * BB;
#pragma unroll
    for (int q = 0; q < 8; q++) {
        int row = r0 + ty * 8 + q;
        float bias = __ldg(bi + row);
        float4 o = make_float4(acc[q][0] + bias, acc[q][1] + bias,
                               acc[q][2] + bias, acc[q][3] + bias);
        *(float4*)(dst + (size_t)row * BB + tx * 4) = o;
    }
}

// ---------------- clustered recurrent scan, warp-MMA bf16 hi/lo ----------------
// 128 CTAs = 16 clusters of 8. CTA: D[128 gate-rows x 8 batch] = W.h per step.
// Warp w owns rows [w*16, w*16+16). W hi/lo A-fragments permanent in registers.
// h converted to bf16 hi/lo B tiles in SMEM each step (row stride 264 bf16).
//
// SMEM byte layout:
//   [0]      h_s  [2][256][8] fp32   16384 B
//   [16384]  bhi  [8][264] bf16       4224 B
//   [20608]  blo  [8][264] bf16       4224 B
//   [24832]  gsm  [128][9] fp32       4608 B
#define SM_HS    0
#define SM_BHI   16384
#define SM_BLO   20608
#define SM_GSM   24832
#define SM_TOTAL 29440
#define BSTB     528          // B tile row stride in bytes (264 bf16)

__global__ void __launch_bounds__(256, 1) __cluster_dims__(CL, 1, 1)
scan_kernel(const float* __restrict__ whh_f, const float* __restrict__ whh_b,
            const float* __restrict__ bhh_f, const float* __restrict__ bhh_b)
{
    extern __shared__ char smc[];
    float* h_s = (float*)(smc + SM_HS);
    float* gsm = (float*)(smc + SM_GSM);

    const int cid  = blockIdx.x >> 3;
    const int rank = blockIdx.x & 7;
    const int dir  = cid >> 3;
    const int b0   = (cid & 7) * BPC;
    const int j0   = rank * JPC;
    const float* whh = dir ? whh_b : whh_f;
    const float* bhh = dir ? bhh_b : bhh_f;
    const int tid  = threadIdx.x;
    const int w    = tid >> 5;
    const int lane = tid & 31;

    // ---- W hi/lo A-fragments in registers ----
    // m1 = w*16 + lane/4, m2 = m1+8 (local rows); k base = ks*16 + (lane%4)*2
    uint32_t ahi[16][4], alo[16][4];
    {
        const int m1 = (w << 4) + (lane >> 2);
        const int m2 = m1 + 8;
        const int g1 = (m1 >> 5) * 256 + j0 + (m1 & 31);
        const int g2 = (m2 >> 5) * 256 + j0 + (m2 & 31);
        const float* wr1 = whh + (size_t)g1 * HH;
        const float* wr2 = whh + (size_t)g2 * HH;
#pragma unroll
        for (int ks = 0; ks < 16; ks++) {
            int kb = ks * 16 + (lane & 3) * 2;
#pragma unroll
            for (int half = 0; half < 2; half++) {       // k offset 0 / +8
                int k = kb + half * 8;
                float a0 = __ldg(wr1 + k),     a1 = __ldg(wr1 + k + 1);
                float b0f = __ldg(wr2 + k),    b1f = __ldg(wr2 + k + 1);
                __nv_bfloat16 a0h = __float2bfloat16_rn(a0);
                __nv_bfloat16 a1h = __float2bfloat16_rn(a1);
                __nv_bfloat16 b0h = __float2bfloat16_rn(b0f);
                __nv_bfloat16 b1h = __float2bfloat16_rn(b1f);
                ahi[ks][half * 2 + 0] = pack_bf16x2(__bfloat162float(a0h), __bfloat162float(a1h));
                ahi[ks][half * 2 + 1] = pack_bf16x2(__bfloat162float(b0h), __bfloat162float(b1h));
                alo[ks][half * 2 + 0] = pack_bf16x2(a0 - __bfloat162float(a0h),
                                                    a1 - __bfloat162float(a1h));
                alo[ks][half * 2 + 1] = pack_bf16x2(b0f - __bfloat162float(b0h),
                                                    b1f - __bfloat162float(b1h));
            }
        }
    }

    // state-phase mapping
    const int jj = tid >> 3;
    const int b  = tid & 7;
    float bh[4];
#pragma unroll
    for (int g = 0; g < 4; g++) bh[g] = __ldg(bhh + g * 256 + j0 + jj);

    // zero h buffer 0; cluster sync before first step
    for (int i = tid; i < 2048; i += 256) h_s[i] = 0.0f;
    __syncthreads();
    asm volatile("barrier.cluster.arrive.aligned;" ::: "memory");
    asm volatile("barrier.cluster.wait.aligned;" ::: "memory");

    // per-thread B-tile pointers (n = lane/4 row; k word = (lane%4))
    const char* bhi_p = smc + SM_BHI + (lane >> 2) * BSTB + (lane & 3) * 4;
    const char* blo_p = smc + SM_BLO + (lane >> 2) * BSTB + (lane & 3) * 4;

    // D-fragment row/col for gsm store
    const int rl1 = (w << 4) + (lane >> 2);
    const int rl2 = rl1 + 8;
    const int n0  = (lane & 3) * 2;

    float c = 0.0f;

    for (int s = 0; s < TT; ++s) {
        const int t = dir ? (TT - 1 - s) : s;
        const int p = s & 1;

        // prefetch x-projection
        float pf[4];
#pragma unroll
        for (int g = 0; g < 4; g++)
            pf[g] = __ldg(g_proj[dir] + ((size_t)t * G4 + g * 256 + j0 + jj) * BB + b0 + b);

        // convert h_s[p] -> bf16 hi/lo B tiles (thread = k row tid, 8 batches)
        {
            const float* hr = h_s + p * 2048 + tid * 8;
            float4 v0 = *(const float4*)hr;
            float4 v1 = *(const float4*)(hr + 4);
            float hv[8] = {v0.x, v0.y, v0.z, v0.w, v1.x, v1.y, v1.z, v1.w};
#pragma unroll
            for (int n = 0; n < 8; n++) {
                __nv_bfloat16 hh = __float2bfloat16_rn(hv[n]);
                __nv_bfloat16 hl = __float2bfloat16_rn(hv[n] - __bfloat162float(hh));
                *(__nv_bfloat16*)(smc + SM_BHI + n * BSTB + tid * 2) = hh;
                *(__nv_bfloat16*)(smc + SM_BLO + n * BSTB + tid * 2) = hl;
            }
        }
        __syncthreads();

        // MMA: D = Whi.hhi + Whi.hlo + Wlo.hhi   (48 HMMA per warp)
        float acc[4] = {0.0f, 0.0f, 0.0f, 0.0f};
#pragma unroll
        for (int ks = 0; ks < 16; ks++) {
            uint32_t bh0 = *(const uint32_t*)(bhi_p + ks * 32);
            uint32_t bh1 = *(const uint32_t*)(bhi_p + ks * 32 + 16);
            uint32_t bl0 = *(const uint32_t*)(blo_p + ks * 32);
            uint32_t bl1 = *(const uint32_t*)(blo_p + ks * 32 + 16);
            mma16816(acc, ahi[ks], bh0, bh1);
            mma16816(acc, ahi[ks], bl0, bl1);
            mma16816(acc, alo[ks], bh0, bh1);
        }

        // write D to gsm[rl][n] (pad 9)
        gsm[rl1 * 9 + n0]     = acc[0];
        gsm[rl1 * 9 + n0 + 1] = acc[1];
        gsm[rl2 * 9 + n0]     = acc[2];
        gsm[rl2 * 9 + n0 + 1] = acc[3];
        __syncthreads();

        // cell: thread (jj, b)
        float gv[4];
#pragma unroll
        for (int g = 0; g < 4; g++)
            gv[g] = pf[g] + bh[g] + gsm[(g * 32 + jj) * 9 + b];
        float i_ = sigf(gv[0]);
        float f_ = sigf(gv[1]);
        float g_ = tanh_fast(gv[2]);
        float o_ = sigf(gv[3]);
        c = f_ * c + i_ * g_;
        float h = o_ * tanh_fast(c);

        // hidden sequence + local publish
        g_hs[((size_t)t * 512 + dir * 256 + j0 + jj) * BB + b0 + b] = h;
        h_s[(p ^ 1) * 2048 + j0 * 8 + tid] = h;       // own slice contiguous
        __syncthreads();

        // DSMEM all-gather own 256-float slice to 7 peers (R6-proven)
        {
            uint32_t lbase = (uint32_t)__cvta_generic_to_shared(h_s + (p ^ 1) * 2048 + j0 * 8);
            const float4* srcv = (const float4*)(h_s + (p ^ 1) * 2048 + j0 * 8);
            for (int i = tid; i < 7 * 64; i += 256) {
                int chunk = i & 63;
                uint32_t dr = (uint32_t)((rank + 1 + (i >> 6)) & 7);
                st_cluster_f4(lbase + chunk * 16, dr, srcv[chunk]);
            }
        }

        // cluster barrier: orders DSMEM stores, gates next step, guards exit
        asm volatile("barrier.cluster.arrive.aligned;" ::: "memory");
        asm volatile("barrier.cluster.wait.aligned;" ::: "memory");
    }
}

// ---------------- final FC ----------------
__global__ void __launch_bounds__(320) fc_kernel(
    const float* __restrict__ fcw, const float* __restrict__ fcb,
    float* __restrict__ out)
{
    const int t = blockIdx.x;
    const int o = threadIdx.x / 64;
    const int b = threadIdx.x & 63;
    const float* hp = g_hs + (size_t)t * 512 * BB + b;
    const float* wp = fcw + o * 512;
    float acc = 0.0f;
#pragma unroll 8
    for (int j = 0; j < 512; j++)
        acc += hp[(size_t)j * BB] * __ldg(wp + j);
    out[((size_t)b * TT + t) * 5 + o] = acc + __ldg(fcb + o);
}

// ---------------- launch ----------------
extern "C" void kernel_launch(void* const* d_in, const int* in_sizes, int n_in,
                              void* d_out, int out_size)
{
    const float* x      = (const float*)d_in[0];
    const float* wih_f  = (const float*)d_in[1];
    const float* whh_f  = (const float*)d_in[2];
    const float* bih_f  = (const float*)d_in[3];
    const float* bhh_f  = (const float*)d_in[4];
    const float* wih_b  = (const float*)d_in[5];
    const float* whh_b  = (const float*)d_in[6];
    const float* bih_b  = (const float*)d_in[7];
    const float* bhh_b  = (const float*)d_in[8];
    const float* fcw    = (const float*)d_in[9];
    const float* fcb    = (const float*)d_in[10];
    float* out = (float*)d_out;

    const int proj_smem = 2 * 136 * 68 * (int)sizeof(float);   // 73,984 B
    cudaFuncSetAttribute(proj_kernel, cudaFuncAttributeMaxDynamicSharedMemorySize, proj_smem);
    cudaFuncSetAttribute(scan_kernel, cudaFuncAttributeMaxDynamicSharedMemorySize, SM_TOTAL);

    dim3 pg(16, TT, 2);
    proj_kernel<<<pg, 128, proj_smem>>>(x, wih_f, wih_b, bih_f, bih_b);

    scan_kernel<<<128, 256, SM_TOTAL>>>(whh_f, whh_b, bhh_f, bhh_b);

    fc_kernel<<<TT, 320>>>(fcw, fcb, out);
}

// round 11
// speedup vs baseline: 3.8829x; 1.3580x over previous
#include <cuda_runtime.h>
#include <cuda_bf16.h>
#include <cstdint>

// Problem constants
#define BB   64
#define TT   1024
#define HH   256
#define DIN  136
#define G4   1024
#define KP   144     // DIN padded to 16-multiple
#define CL   8       // cluster size
#define BPC  8       // batches per cluster
#define JPC  32      // hidden units per CTA

// ---------------- scratch ----------------
__device__ __align__(16) float g_proj[2][(size_t)TT * G4 * BB]; // [dir][t][row][b]
__device__ __align__(16) float g_hs[(size_t)TT * 2 * HH * BB];  // [t][dir*H+j][b]
__device__ __align__(16) __nv_bfloat16 g_xhi[(size_t)TT * BB * KP]; // [t][b][k]
__device__ __align__(16) __nv_bfloat16 g_xlo[(size_t)TT * BB * KP];
__device__ __align__(16) __nv_bfloat16 g_whi[2][(size_t)G4 * KP];   // [dir][row][k]
__device__ __align__(16) __nv_bfloat16 g_wlo[2][(size_t)G4 * KP];

// ---------------- activations ----------------
__device__ __forceinline__ float sigf(float x) { return 1.0f / (1.0f + __expf(-x)); }
__device__ __forceinline__ float tanh_fast(float x) {
    float xx = fminf(fmaxf(x, -10.0f), 10.0f);
    float e = __expf(2.0f * xx);
    return (e - 1.0f) / (e + 1.0f);
}

// ---------------- DSMEM float4 store to peer rank ----------------
__device__ __forceinline__ void st_cluster_f4(uint32_t laddr, uint32_t rank, float4 v) {
    asm volatile(
        "{\n\t.reg .b32 r;\n\t"
        "mapa.shared::cluster.u32 r, %0, %1;\n\t"
        "st.shared::cluster.v4.f32 [r], {%2, %3, %4, %5};\n\t}"
        :: "r"(laddr), "r"(rank), "f"(v.x), "f"(v.y), "f"(v.z), "f"(v.w) : "memory");
}

// ---------------- warp-level bf16 MMA ----------------
__device__ __forceinline__ void mma16816(float* d, const uint32_t* a,
                                         uint32_t b0, uint32_t b1) {
    asm volatile(
        "mma.sync.aligned.m16n8k16.row.col.f32.bf16.bf16.f32 "
        "{%0,%1,%2,%3}, {%4,%5,%6,%7}, {%8,%9}, {%0,%1,%2,%3};"
        : "+f"(d[0]), "+f"(d[1]), "+f"(d[2]), "+f"(d[3])
        : "r"(a[0]), "r"(a[1]), "r"(a[2]), "r"(a[3]), "r"(b0), "r"(b1));
}
__device__ __forceinline__ uint32_t pack_bf16x2(float lo, float hi) {
    __nv_bfloat162 t = __floats2bfloat162_rn(lo, hi);
    return *(uint32_t*)&t;
}

// ---------------- conversion kernels (one-time, trivial) ----------------
__global__ void conv_x_kernel(const float* __restrict__ x) {
    const int t = blockIdx.x;
    for (int idx = threadIdx.x; idx < BB * KP; idx += 256) {
        int b = idx / KP, k = idx - b * KP;
        float v = (k < DIN) ? __ldg(x + ((size_t)b * TT + t) * DIN + k) : 0.0f;
        __nv_bfloat16 hi = __float2bfloat16_rn(v);
        __nv_bfloat16 lo = __float2bfloat16_rn(v - __bfloat162float(hi));
        size_t o = ((size_t)t * BB + b) * KP + k;
        g_xhi[o] = hi; g_xlo[o] = lo;
    }
}
__global__ void conv_w_kernel(const float* __restrict__ wf, const float* __restrict__ wb) {
    const int row = blockIdx.x;
    const int dir = blockIdx.y;
    const float* w = dir ? wb : wf;
    for (int k = threadIdx.x; k < KP; k += 160) {
        float v = (k < DIN) ? __ldg(w + (size_t)row * DIN + k) : 0.0f;
        __nv_bfloat16 hi = __float2bfloat16_rn(v);
        __nv_bfloat16 lo = __float2bfloat16_rn(v - __bfloat162float(hi));
        size_t o = (size_t)row * KP + k;
        g_whi[dir][o] = hi; g_wlo[dir][o] = lo;
    }
}

// ---------------- input projection via warp MMA (bf16 hi/lo 3-split) --------------
// CTA: 64 rows x 64 batches, one (t, dir). 4 warps, warp = 16 rows.
// A-frags (W) in registers; B (x) staged hi/lo in SMEM, row stride 152 bf16.
#define PBST 304   // B row stride bytes (152 bf16)
__global__ void __launch_bounds__(128, 3) proj_mma_kernel(
    const float* __restrict__ bih_f, const float* __restrict__ bih_b)
{
    extern __shared__ char psm[];   // bhi [64][152] bf16 (19456 B) + blo (19456 B)
    char* sbhi = psm;
    char* sblo = psm + 19456;

    const int r0  = blockIdx.x * 64;
    const int t   = blockIdx.y;
    const int dir = blockIdx.z;
    const int tid = threadIdx.x;
    const int w   = tid >> 5;
    const int lane = tid & 31;

    // ---- A-fragments from gmem (validated R9 pack order) ----
    const int m1 = (w << 4) + (lane >> 2);
    const int m2 = m1 + 8;
    const __nv_bfloat16* wh1 = g_whi[dir] + (size_t)(r0 + m1) * KP;
    const __nv_bfloat16* wh2 = g_whi[dir] + (size_t)(r0 + m2) * KP;
    const __nv_bfloat16* wl1 = g_wlo[dir] + (size_t)(r0 + m1) * KP;
    const __nv_bfloat16* wl2 = g_wlo[dir] + (size_t)(r0 + m2) * KP;
    uint32_t ahi[9][4], alo[9][4];
#pragma unroll
    for (int ch = 0; ch < 9; ch++) {
        int kb = ch * 16 + (lane & 3) * 2;
        ahi[ch][0] = *(const uint32_t*)(wh1 + kb);
        ahi[ch][1] = *(const uint32_t*)(wh2 + kb);
        ahi[ch][2] = *(const uint32_t*)(wh1 + kb + 8);
        ahi[ch][3] = *(const uint32_t*)(wh2 + kb + 8);
        alo[ch][0] = *(const uint32_t*)(wl1 + kb);
        alo[ch][1] = *(const uint32_t*)(wl2 + kb);
        alo[ch][2] = *(const uint32_t*)(wl1 + kb + 8);
        alo[ch][3] = *(const uint32_t*)(wl2 + kb + 8);
    }

    // ---- stage B tile (x for this t): 64 rows x 144 bf16, hi+lo ----
    {
        const uint4* xh = (const uint4*)(g_xhi + (size_t)t * BB * KP);
        const uint4* xl = (const uint4*)(g_xlo + (size_t)t * BB * KP);
        for (int idx = tid; idx < 64 * 18; idx += 128) {
            int b = idx / 18, kk = idx - b * 18;       // kk: 8-bf16 chunk
            uint4 vh = __ldg(xh + b * 18 + kk);
            uint4 vl = __ldg(xl + b * 18 + kk);
            *(uint4*)(sbhi + b * PBST + kk * 16) = vh;
            *(uint4*)(sblo + b * PBST + kk * 16) = vl;
        }
    }
    __syncthreads();

    // ---- MMA: 8 n-tiles x 9 k-chunks x 3 splits ----
    float acc[8][4];
#pragma unroll
    for (int nt = 0; nt < 8; nt++)
#pragma unroll
        for (int i = 0; i < 4; i++) acc[nt][i] = 0.0f;

    const char* bhp = sbhi + (lane >> 2) * PBST + (lane & 3) * 4;
    const char* blp = sblo + (lane >> 2) * PBST + (lane & 3) * 4;
#pragma unroll
    for (int ch = 0; ch < 9; ch++) {
#pragma unroll
        for (int nt = 0; nt < 8; nt++) {
            int off = nt * 8 * PBST + ch * 32;
            uint32_t bh0 = *(const uint32_t*)(bhp + off);
            uint32_t bh1 = *(const uint32_t*)(bhp + off + 16);
            uint32_t bl0 = *(const uint32_t*)(blp + off);
            uint32_t bl1 = *(const uint32_t*)(blp + off + 16);
            mma16816(acc[nt], ahi[ch], bh0, bh1);
            mma16816(acc[nt], ahi[ch], bl0, bl1);
            mma16816(acc[nt], alo[ch], bh0, bh1);
        }
    }

    // ---- epilogue: bias + store to g_proj[dir][t][row][b] ----
    const float* bi = dir ? bih_b : bih_f;
    float bias1 = __ldg(bi + r0 + m1);
    float bias2 = __ldg(bi + r0 + m2);
    float* dst = g_proj[dir] + (size_t)t * G4 * BB;
    const int n0 = (lane & 3) * 2;
#pragma unroll
    for (int nt = 0; nt < 8; nt++) {
        int n = nt * 8 + n0;
        *(float2*)(dst + (size_t)(r0 + m1) * BB + n) =
            make_float2(acc[nt][0] + bias1, acc[nt][1] + bias1);
        *(float2*)(dst + (size_t)(r0 + m2) * BB + n) =
            make_float2(acc[nt][2] + bias2, acc[nt][3] + bias2);
    }
}

// ---------------- clustered recurrent scan, warp-MMA bf16 hi/lo (R9 + acc split) --
#define SM_HS    0
#define SM_BHI   16384
#define SM_BLO   20608
#define SM_GSM   24832
#define SM_TOTAL 29440
#define BSTB     528

__global__ void __launch_bounds__(256, 1) __cluster_dims__(CL, 1, 1)
scan_kernel(const float* __restrict__ whh_f, const float* __restrict__ whh_b,
            const float* __restrict__ bhh_f, const float* __restrict__ bhh_b)
{
    extern __shared__ char smc[];
    float* h_s = (float*)(smc + SM_HS);
    float* gsm = (float*)(smc + SM_GSM);

    const int cid  = blockIdx.x >> 3;
    const int rank = blockIdx.x & 7;
    const int dir  = cid >> 3;
    const int b0   = (cid & 7) * BPC;
    const int j0   = rank * JPC;
    const float* whh = dir ? whh_b : whh_f;
    const float* bhh = dir ? bhh_b : bhh_f;
    const int tid  = threadIdx.x;
    const int w    = tid >> 5;
    const int lane = tid & 31;

    // W hi/lo A-fragments in registers (R9-validated layout)
    uint32_t ahi[16][4], alo[16][4];
    {
        const int m1 = (w << 4) + (lane >> 2);
        const int m2 = m1 + 8;
        const int g1 = (m1 >> 5) * 256 + j0 + (m1 & 31);
        const int g2 = (m2 >> 5) * 256 + j0 + (m2 & 31);
        const float* wr1 = whh + (size_t)g1 * HH;
        const float* wr2 = whh + (size_t)g2 * HH;
#pragma unroll
        for (int ks = 0; ks < 16; ks++) {
            int kb = ks * 16 + (lane & 3) * 2;
#pragma unroll
            for (int half = 0; half < 2; half++) {
                int k = kb + half * 8;
                float a0 = __ldg(wr1 + k),  a1 = __ldg(wr1 + k + 1);
                float b0f = __ldg(wr2 + k), b1f = __ldg(wr2 + k + 1);
                __nv_bfloat16 a0h = __float2bfloat16_rn(a0);
                __nv_bfloat16 a1h = __float2bfloat16_rn(a1);
                __nv_bfloat16 b0h = __float2bfloat16_rn(b0f);
                __nv_bfloat16 b1h = __float2bfloat16_rn(b1f);
                ahi[ks][half * 2 + 0] = pack_bf16x2(__bfloat162float(a0h), __bfloat162float(a1h));
                ahi[ks][half * 2 + 1] = pack_bf16x2(__bfloat162float(b0h), __bfloat162float(b1h));
                alo[ks][half * 2 + 0] = pack_bf16x2(a0 - __bfloat162float(a0h),
                                                    a1 - __bfloat162float(a1h));
                alo[ks][half * 2 + 1] = pack_bf16x2(b0f - __bfloat162float(b0h),
                                                    b1f - __bfloat162float(b1h));
            }
        }
    }

    const int jj = tid >> 3;
    const int b  = tid & 7;
    float bh[4];
#pragma unroll
    for (int g = 0; g < 4; g++) bh[g] = __ldg(bhh + g * 256 + j0 + jj);

    for (int i = tid; i < 2048; i += 256) h_s[i] = 0.0f;
    __syncthreads();
    asm volatile("barrier.cluster.arrive.aligned;" ::: "memory");
    asm volatile("barrier.cluster.wait.aligned;" ::: "memory");

    const char* bhi_p = smc + SM_BHI + (lane >> 2) * BSTB + (lane & 3) * 4;
    const char* blo_p = smc + SM_BLO + (lane >> 2) * BSTB + (lane & 3) * 4;
    const int rl1 = (w << 4) + (lane >> 2);
    const int rl2 = rl1 + 8;
    const int n0  = (lane & 3) * 2;

    float c = 0.0f;

    for (int s = 0; s < TT; ++s) {
        const int t = dir ? (TT - 1 - s) : s;
        const int p = s & 1;

        float pf[4];
#pragma unroll
        for (int g = 0; g < 4; g++)
            pf[g] = __ldg(g_proj[dir] + ((size_t)t * G4 + g * 256 + j0 + jj) * BB + b0 + b);

        // convert h -> bf16 hi/lo B tiles
        {
            const float* hr = h_s + p * 2048 + tid * 8;
            float4 v0 = *(const float4*)hr;
            float4 v1 = *(const float4*)(hr + 4);
            float hv[8] = {v0.x, v0.y, v0.z, v0.w, v1.x, v1.y, v1.z, v1.w};
#pragma unroll
            for (int n = 0; n < 8; n++) {
                __nv_bfloat16 hh = __float2bfloat16_rn(hv[n]);
                __nv_bfloat16 hl = __float2bfloat16_rn(hv[n] - __bfloat162float(hh));
                *(__nv_bfloat16*)(smc + SM_BHI + n * BSTB + tid * 2) = hh;
                *(__nv_bfloat16*)(smc + SM_BLO + n * BSTB + tid * 2) = hl;
            }
        }
        __syncthreads();

        // MMA with 3 independent accumulator chains (depth 16 each)
        float accA[4] = {0, 0, 0, 0}, accB[4] = {0, 0, 0, 0}, accC[4] = {0, 0, 0, 0};
#pragma unroll
        for (int ks = 0; ks < 16; ks++) {
            uint32_t bh0 = *(const uint32_t*)(bhi_p + ks * 32);
            uint32_t bh1 = *(const uint32_t*)(bhi_p + ks * 32 + 16);
            uint32_t bl0 = *(const uint32_t*)(blo_p + ks * 32);
            uint32_t bl1 = *(const uint32_t*)(blo_p + ks * 32 + 16);
            mma16816(accA, ahi[ks], bh0, bh1);
            mma16816(accB, ahi[ks], bl0, bl1);
            mma16816(accC, alo[ks], bh0, bh1);
        }

        gsm[rl1 * 9 + n0]     = accA[0] + accB[0] + accC[0];
        gsm[rl1 * 9 + n0 + 1] = accA[1] + accB[1] + accC[1];
        gsm[rl2 * 9 + n0]     = accA[2] + accB[2] + accC[2];
        gsm[rl2 * 9 + n0 + 1] = accA[3] + accB[3] + accC[3];
        __syncthreads();

        float gv[4];
#pragma unroll
        for (int g = 0; g < 4; g++)
            gv[g] = pf[g] + bh[g] + gsm[(g * 32 + jj) * 9 + b];
        float i_ = sigf(gv[0]);
        float f_ = sigf(gv[1]);
        float g_ = tanh_fast(gv[2]);
        float o_ = sigf(gv[3]);
        c = f_ * c + i_ * g_;
        float h = o_ * tanh_fast(c);

        g_hs[((size_t)t * 512 + dir * 256 + j0 + jj) * BB + b0 + b] = h;
        h_s[(p ^ 1) * 2048 + j0 * 8 + tid] = h;
        __syncthreads();

        {
            uint32_t lbase = (uint32_t)__cvta_generic_to_shared(h_s + (p ^ 1) * 2048 + j0 * 8);
            const float4* srcv = (const float4*)(h_s + (p ^ 1) * 2048 + j0 * 8);
            for (int i = tid; i < 7 * 64; i += 256) {
                int chunk = i & 63;
                uint32_t dr = (uint32_t)((rank + 1 + (i >> 6)) & 7);
                st_cluster_f4(lbase + chunk * 16, dr, srcv[chunk]);
            }
        }

        asm volatile("barrier.cluster.arrive.aligned;" ::: "memory");
        asm volatile("barrier.cluster.wait.aligned;" ::: "memory");
    }
}

// ---------------- final FC ----------------
__global__ void __launch_bounds__(320) fc_kernel(
    const float* __restrict__ fcw, const float* __restrict__ fcb,
    float* __restrict__ out)
{
    const int t = blockIdx.x;
    const int o = threadIdx.x / 64;
    const int b = threadIdx.x & 63;
    const float* hp = g_hs + (size_t)t * 512 * BB + b;
    const float* wp = fcw + o * 512;
    float acc = 0.0f;
#pragma unroll 8
    for (int j = 0; j < 512; j++)
        acc += hp[(size_t)j * BB] * __ldg(wp + j);
    out[((size_t)b * TT + t) * 5 + o] = acc + __ldg(fcb + o);
}

// ---------------- launch ----------------
extern "C" void kernel_launch(void* const* d_in, const int* in_sizes, int n_in,
                              void* d_out, int out_size)
{
    const float* x      = (const float*)d_in[0];
    const float* wih_f  = (const float*)d_in[1];
    const float* whh_f  = (const float*)d_in[2];
    const float* bih_f  = (const float*)d_in[3];
    const float* bhh_f  = (const float*)d_in[4];
    const float* wih_b  = (const float*)d_in[5];
    const float* whh_b  = (const float*)d_in[6];
    const float* bih_b  = (const float*)d_in[7];
    const float* bhh_b  = (const float*)d_in[8];
    const float* fcw    = (const float*)d_in[9];
    const float* fcb    = (const float*)d_in[10];
    float* out = (float*)d_out;

    const int pm_smem = 2 * 19456;   // 38,912 B
    cudaFuncSetAttribute(proj_mma_kernel, cudaFuncAttributeMaxDynamicSharedMemorySize, pm_smem);
    cudaFuncSetAttribute(scan_kernel, cudaFuncAttributeMaxDynamicSharedMemorySize, SM_TOTAL);

    conv_x_kernel<<<TT, 256>>>(x);
    conv_w_kernel<<<dim3(G4, 2), 160>>>(wih_f, wih_b);

    dim3 pg(16, TT, 2);
    proj_mma_kernel<<<pg, 128, pm_smem>>>(bih_f, bih_b);

    scan_kernel<<<128, 256, SM_TOTAL>>>(whh_f, whh_b, bhh_f, bhh_b);

    fc_kernel<<<TT, 320>>>(fcw, fcb, out);
}

// round 12
// speedup vs baseline: 4.2299x; 1.0894x over previous
#include <cuda_runtime.h>
#include <cuda_bf16.h>
#include <cstdint>

// Problem constants
#define BB   64
#define TT   1024
#define HH   256
#define DIN  136
#define G4   1024
#define KP   144     // DIN padded to 16-multiple
#define CL   8       // cluster size
#define BPC  8       // batches per cluster
#define JPC  32      // hidden units per CTA

// ---------------- scratch ----------------
__device__ __align__(16) float g_proj[2][(size_t)TT * G4 * BB]; // [dir][t][row][b]
__device__ __align__(16) float g_hs[(size_t)TT * 2 * HH * BB];  // [t][dir*H+j][b]
__device__ __align__(16) __nv_bfloat16 g_xhi[(size_t)TT * BB * KP]; // [t][b][k]
__device__ __align__(16) __nv_bfloat16 g_xlo[(size_t)TT * BB * KP];
__device__ __align__(16) __nv_bfloat16 g_whi[2][(size_t)G4 * KP];   // [dir][row][k]
__device__ __align__(16) __nv_bfloat16 g_wlo[2][(size_t)G4 * KP];

// ---------------- activations ----------------
__device__ __forceinline__ float sigf(float x) { return 1.0f / (1.0f + __expf(-x)); }
__device__ __forceinline__ float tanh_fast(float x) {
    float xx = fminf(fmaxf(x, -10.0f), 10.0f);
    float e = __expf(2.0f * xx);
    return (e - 1.0f) / (e + 1.0f);
}

// ---------------- DSMEM float4 store to peer rank ----------------
__device__ __forceinline__ void st_cluster_f4(uint32_t laddr, uint32_t rank, uint4 v) {
    asm volatile(
        "{\n\t.reg .b32 r;\n\t"
        "mapa.shared::cluster.u32 r, %0, %1;\n\t"
        "st.shared::cluster.v4.b32 [r], {%2, %3, %4, %5};\n\t}"
        :: "r"(laddr), "r"(rank), "r"(v.x), "r"(v.y), "r"(v.z), "r"(v.w) : "memory");
}

// ---------------- warp-level bf16 MMA ----------------
__device__ __forceinline__ void mma16816(float* d, const uint32_t* a,
                                         uint32_t b0, uint32_t b1) {
    asm volatile(
        "mma.sync.aligned.m16n8k16.row.col.f32.bf16.bf16.f32 "
        "{%0,%1,%2,%3}, {%4,%5,%6,%7}, {%8,%9}, {%0,%1,%2,%3};"
        : "+f"(d[0]), "+f"(d[1]), "+f"(d[2]), "+f"(d[3])
        : "r"(a[0]), "r"(a[1]), "r"(a[2]), "r"(a[3]), "r"(b0), "r"(b1));
}
__device__ __forceinline__ uint32_t pack_bf16x2(float lo, float hi) {
    __nv_bfloat162 t = __floats2bfloat162_rn(lo, hi);
    return *(uint32_t*)&t;
}

// ---------------- conversion kernels (one-time, trivial) ----------------
__global__ void conv_x_kernel(const float* __restrict__ x) {
    const int t = blockIdx.x;
    for (int idx = threadIdx.x; idx < BB * KP; idx += 256) {
        int b = idx / KP, k = idx - b * KP;
        float v = (k < DIN) ? __ldg(x + ((size_t)b * TT + t) * DIN + k) : 0.0f;
        __nv_bfloat16 hi = __float2bfloat16_rn(v);
        __nv_bfloat16 lo = __float2bfloat16_rn(v - __bfloat162float(hi));
        size_t o = ((size_t)t * BB + b) * KP + k;
        g_xhi[o] = hi; g_xlo[o] = lo;
    }
}
__global__ void conv_w_kernel(const float* __restrict__ wf, const float* __restrict__ wb) {
    const int row = blockIdx.x;
    const int dir = blockIdx.y;
    const float* w = dir ? wb : wf;
    for (int k = threadIdx.x; k < KP; k += 160) {
        float v = (k < DIN) ? __ldg(w + (size_t)row * DIN + k) : 0.0f;
        __nv_bfloat16 hi = __float2bfloat16_rn(v);
        __nv_bfloat16 lo = __float2bfloat16_rn(v - __bfloat162float(hi));
        size_t o = (size_t)row * KP + k;
        g_whi[dir][o] = hi; g_wlo[dir][o] = lo;
    }
}

// ---------------- input projection via warp MMA (R10, known-good) ----------------
#define PBST 304   // B row stride bytes (152 bf16)
__global__ void __launch_bounds__(128, 3) proj_mma_kernel(
    const float* __restrict__ bih_f, const float* __restrict__ bih_b)
{
    extern __shared__ char psm[];
    char* sbhi = psm;
    char* sblo = psm + 19456;

    const int r0  = blockIdx.x * 64;
    const int t   = blockIdx.y;
    const int dir = blockIdx.z;
    const int tid = threadIdx.x;
    const int w   = tid >> 5;
    const int lane = tid & 31;

    const int m1 = (w << 4) + (lane >> 2);
    const int m2 = m1 + 8;
    const __nv_bfloat16* wh1 = g_whi[dir] + (size_t)(r0 + m1) * KP;
    const __nv_bfloat16* wh2 = g_whi[dir] + (size_t)(r0 + m2) * KP;
    const __nv_bfloat16* wl1 = g_wlo[dir] + (size_t)(r0 + m1) * KP;
    const __nv_bfloat16* wl2 = g_wlo[dir] + (size_t)(r0 + m2) * KP;
    uint32_t ahi[9][4], alo[9][4];
#pragma unroll
    for (int ch = 0; ch < 9; ch++) {
        int kb = ch * 16 + (lane & 3) * 2;
        ahi[ch][0] = *(const uint32_t*)(wh1 + kb);
        ahi[ch][1] = *(const uint32_t*)(wh2 + kb);
        ahi[ch][2] = *(const uint32_t*)(wh1 + kb + 8);
        ahi[ch][3] = *(const uint32_t*)(wh2 + kb + 8);
        alo[ch][0] = *(const uint32_t*)(wl1 + kb);
        alo[ch][1] = *(const uint32_t*)(wl2 + kb);
        alo[ch][2] = *(const uint32_t*)(wl1 + kb + 8);
        alo[ch][3] = *(const uint32_t*)(wl2 + kb + 8);
    }

    {
        const uint4* xh = (const uint4*)(g_xhi + (size_t)t * BB * KP);
        const uint4* xl = (const uint4*)(g_xlo + (size_t)t * BB * KP);
        for (int idx = tid; idx < 64 * 18; idx += 128) {
            int b = idx / 18, kk = idx - b * 18;
            uint4 vh = __ldg(xh + b * 18 + kk);
            uint4 vl = __ldg(xl + b * 18 + kk);
            *(uint4*)(sbhi + b * PBST + kk * 16) = vh;
            *(uint4*)(sblo + b * PBST + kk * 16) = vl;
        }
    }
    __syncthreads();

    float acc[8][4];
#pragma unroll
    for (int nt = 0; nt < 8; nt++)
#pragma unroll
        for (int i = 0; i < 4; i++) acc[nt][i] = 0.0f;

    const char* bhp = sbhi + (lane >> 2) * PBST + (lane & 3) * 4;
    const char* blp = sblo + (lane >> 2) * PBST + (lane & 3) * 4;
#pragma unroll
    for (int ch = 0; ch < 9; ch++) {
#pragma unroll
        for (int nt = 0; nt < 8; nt++) {
            int off = nt * 8 * PBST + ch * 32;
            uint32_t bh0 = *(const uint32_t*)(bhp + off);
            uint32_t bh1 = *(const uint32_t*)(bhp + off + 16);
            uint32_t bl0 = *(const uint32_t*)(blp + off);
            uint32_t bl1 = *(const uint32_t*)(blp + off + 16);
            mma16816(acc[nt], ahi[ch], bh0, bh1);
            mma16816(acc[nt], ahi[ch], bl0, bl1);
            mma16816(acc[nt], alo[ch], bh0, bh1);
        }
    }

    const float* bi = dir ? bih_b : bih_f;
    float bias1 = __ldg(bi + r0 + m1);
    float bias2 = __ldg(bi + r0 + m2);
    float* dst = g_proj[dir] + (size_t)t * G4 * BB;
    const int n0 = (lane & 3) * 2;
#pragma unroll
    for (int nt = 0; nt < 8; nt++) {
        int n = nt * 8 + n0;
        *(float2*)(dst + (size_t)(r0 + m1) * BB + n) =
            make_float2(acc[nt][0] + bias1, acc[nt][1] + bias1);
        *(float2*)(dst + (size_t)(r0 + m2) * BB + n) =
            make_float2(acc[nt][2] + bias2, acc[nt][3] + bias2);
    }
}

// ---------------- clustered recurrent scan: bf16 exchange, double-buffered B ------
// SMEM byte layout:
//   [0]      B tiles [2 parity][hi 8x264 | lo 8x264] bf16   2*8448 = 16896 B
//   [16896]  stg: own-slice hi[8][32] + lo[8][32] bf16        1024 B
//   [17920]  gsm [128][9] fp32                                 4608 B
#define PAR_SZ   8448
#define SM_STG   16896
#define SM_GSM   17920
#define SM_TOTAL 22528
#define BSTB     528

__global__ void __launch_bounds__(256, 1) __cluster_dims__(CL, 1, 1)
scan_kernel(const float* __restrict__ whh_f, const float* __restrict__ whh_b,
            const float* __restrict__ bhh_f, const float* __restrict__ bhh_b)
{
    extern __shared__ char smc[];
    float* gsm = (float*)(smc + SM_GSM);
    const uint32_t smem_u32 = (uint32_t)__cvta_generic_to_shared(smc);

    const int cid  = blockIdx.x >> 3;
    const int rank = blockIdx.x & 7;
    const int dir  = cid >> 3;
    const int b0   = (cid & 7) * BPC;
    const int j0   = rank * JPC;
    const float* whh = dir ? whh_b : whh_f;
    const float* bhh = dir ? bhh_b : bhh_f;
    const int tid  = threadIdx.x;
    const int w    = tid >> 5;
    const int lane = tid & 31;

    // W hi/lo A-fragments in registers (R9/R10-validated layout)
    uint32_t ahi[16][4], alo[16][4];
    {
        const int m1 = (w << 4) + (lane >> 2);
        const int m2 = m1 + 8;
        const int g1 = (m1 >> 5) * 256 + j0 + (m1 & 31);
        const int g2 = (m2 >> 5) * 256 + j0 + (m2 & 31);
        const float* wr1 = whh + (size_t)g1 * HH;
        const float* wr2 = whh + (size_t)g2 * HH;
#pragma unroll
        for (int ks = 0; ks < 16; ks++) {
            int kb = ks * 16 + (lane & 3) * 2;
#pragma unroll
            for (int half = 0; half < 2; half++) {
                int k = kb + half * 8;
                float a0 = __ldg(wr1 + k),  a1 = __ldg(wr1 + k + 1);
                float b0f = __ldg(wr2 + k), b1f = __ldg(wr2 + k + 1);
                __nv_bfloat16 a0h = __float2bfloat16_rn(a0);
                __nv_bfloat16 a1h = __float2bfloat16_rn(a1);
                __nv_bfloat16 b0h = __float2bfloat16_rn(b0f);
                __nv_bfloat16 b1h = __float2bfloat16_rn(b1f);
                ahi[ks][half * 2 + 0] = pack_bf16x2(__bfloat162float(a0h), __bfloat162float(a1h));
                ahi[ks][half * 2 + 1] = pack_bf16x2(__bfloat162float(b0h), __bfloat162float(b1h));
                alo[ks][half * 2 + 0] = pack_bf16x2(a0 - __bfloat162float(a0h),
                                                    a1 - __bfloat162float(a1h));
                alo[ks][half * 2 + 1] = pack_bf16x2(b0f - __bfloat162float(b0h),
                                                    b1f - __bfloat162float(b1h));
            }
        }
    }

    const int jj = tid >> 3;
    const int b  = tid & 7;
    float bh[4];
#pragma unroll
    for (int g = 0; g < 4; g++) bh[g] = __ldg(bhh + g * 256 + j0 + jj);

    // zero both B parities (h=0 initial state)
    for (int i = tid; i < (2 * PAR_SZ) / 4; i += 256) ((uint32_t*)smc)[i] = 0u;
    __syncthreads();
    asm volatile("barrier.cluster.arrive.aligned;" ::: "memory");
    asm volatile("barrier.cluster.wait.aligned;" ::: "memory");

    const int lane_off = (lane >> 2) * BSTB + (lane & 3) * 4;
    const int rl1 = (w << 4) + (lane >> 2);
    const int rl2 = rl1 + 8;
    const int n0  = (lane & 3) * 2;

    float c = 0.0f;

    // initial proj prefetch (s=0)
    float pf[4];
    {
        const int t0 = dir ? (TT - 1) : 0;
#pragma unroll
        for (int g = 0; g < 4; g++)
            pf[g] = __ldg(g_proj[dir] + ((size_t)t0 * G4 + g * 256 + j0 + jj) * BB + b0 + b);
    }

    for (int s = 0; s < TT; ++s) {
        const int t = dir ? (TT - 1 - s) : s;
        const int p = s & 1;

        // MMA on B[p] (complete per cluster barrier of previous step)
        const char* bhi_p = smc + p * PAR_SZ + lane_off;
        const char* blo_p = bhi_p + 4224;
        float accA[4] = {0, 0, 0, 0}, accB[4] = {0, 0, 0, 0}, accC[4] = {0, 0, 0, 0};
#pragma unroll
        for (int ks = 0; ks < 16; ks++) {
            uint32_t bh0 = *(const uint32_t*)(bhi_p + ks * 32);
            uint32_t bh1 = *(const uint32_t*)(bhi_p + ks * 32 + 16);
            uint32_t bl0 = *(const uint32_t*)(blo_p + ks * 32);
            uint32_t bl1 = *(const uint32_t*)(blo_p + ks * 32 + 16);
            mma16816(accA, ahi[ks], bh0, bh1);
            mma16816(accB, ahi[ks], bl0, bl1);
            mma16816(accC, alo[ks], bh0, bh1);
        }
        gsm[rl1 * 9 + n0]     = accA[0] + accB[0] + accC[0];
        gsm[rl1 * 9 + n0 + 1] = accA[1] + accB[1] + accC[1];
        gsm[rl2 * 9 + n0]     = accA[2] + accB[2] + accC[2];
        gsm[rl2 * 9 + n0 + 1] = accA[3] + accB[3] + accC[3];
        __syncthreads();

        // cell: thread (jj, b)
        float gv[4];
#pragma unroll
        for (int g = 0; g < 4; g++)
            gv[g] = pf[g] + bh[g] + gsm[(g * 32 + jj) * 9 + b];
        float i_ = sigf(gv[0]);
        float f_ = sigf(gv[1]);
        float g_ = tanh_fast(gv[2]);
        float o_ = sigf(gv[3]);
        c = f_ * c + i_ * g_;
        float h = o_ * tanh_fast(c);

        // hidden sequence (global fp32)
        g_hs[((size_t)t * 512 + dir * 256 + j0 + jj) * BB + b0 + b] = h;

        // convert own h once; stage into own-slice bf16 tile (hi/lo)
        {
            __nv_bfloat16 hh = __float2bfloat16_rn(h);
            __nv_bfloat16 hl = __float2bfloat16_rn(h - __bfloat162float(hh));
            *(__nv_bfloat16*)(smc + SM_STG + b * 64 + jj * 2) = hh;
            *(__nv_bfloat16*)(smc + SM_STG + 512 + b * 64 + jj * 2) = hl;
        }
        __syncthreads();

        // scatter own slice into B[p^1] of all 8 ranks (2 float4/thread)
#pragma unroll
        for (int rep = 0; rep < 2; rep++) {
            int i = tid + rep * 256;
            int chunk = i & 63;
            int ro = i >> 6;                       // 0..7 (0 = self)
            int hl = chunk >> 5;
            int bb = (chunk >> 2) & 7;
            int cc = chunk & 3;
            uint4 v = *(const uint4*)(smc + SM_STG + hl * 512 + bb * 64 + cc * 16);
            uint32_t dstoff = (uint32_t)((p ^ 1) * PAR_SZ + hl * 4224 + bb * BSTB
                                         + j0 * 2 + cc * 16);
            st_cluster_f4(smem_u32 + dstoff, (uint32_t)((rank + ro) & 7), v);
        }

        // split cluster barrier; prefetch next proj between arrive and wait
        asm volatile("barrier.cluster.arrive.aligned;" ::: "memory");
        if (s + 1 < TT) {
            const int tn = dir ? (TT - 2 - s) : (s + 1);
#pragma unroll
            for (int g = 0; g < 4; g++)
                pf[g] = __ldg(g_proj[dir] + ((size_t)tn * G4 + g * 256 + j0 + jj) * BB + b0 + b);
        }
        asm volatile("barrier.cluster.wait.aligned;" ::: "memory");
    }
}

// ---------------- final FC ----------------
__global__ void __launch_bounds__(320) fc_kernel(
    const float* __restrict__ fcw, const float* __restrict__ fcb,
    float* __restrict__ out)
{
    const int t = blockIdx.x;
    const int o = threadIdx.x / 64;
    const int b = threadIdx.x & 63;
    const float* hp = g_hs + (size_t)t * 512 * BB + b;
    const float* wp = fcw + o * 512;
    float acc = 0.0f;
#pragma unroll 8
    for (int j = 0; j < 512; j++)
        acc += hp[(size_t)j * BB] * __ldg(wp + j);
    out[((size_t)b * TT + t) * 5 + o] = acc + __ldg(fcb + o);
}

// ---------------- launch ----------------
extern "C" void kernel_launch(void* const* d_in, const int* in_sizes, int n_in,
                              void* d_out, int out_size)
{
    const float* x      = (const float*)d_in[0];
    const float* wih_f  = (const float*)d_in[1];
    const float* whh_f  = (const float*)d_in[2];
    const float* bih_f  = (const float*)d_in[3];
    const float* bhh_f  = (const float*)d_in[4];
    const float* wih_b  = (const float*)d_in[5];
    const float* whh_b  = (const float*)d_in[6];
    const float* bih_b  = (const float*)d_in[7];
    const float* bhh_b  = (const float*)d_in[8];
    const float* fcw    = (const float*)d_in[9];
    const float* fcb    = (const float*)d_in[10];
    float* out = (float*)d_out;

    const int pm_smem = 2 * 19456;
    cudaFuncSetAttribute(proj_mma_kernel, cudaFuncAttributeMaxDynamicSharedMemorySize, pm_smem);
    cudaFuncSetAttribute(scan_kernel, cudaFuncAttributeMaxDynamicSharedMemorySize, SM_TOTAL);

    conv_x_kernel<<<TT, 256>>>(x);
    conv_w_kernel<<<dim3(G4, 2), 160>>>(wih_f, wih_b);

    dim3 pg(16, TT, 2);
    proj_mma_kernel<<<pg, 128, pm_smem>>>(bih_f, bih_b);

    scan_kernel<<<128, 256, SM_TOTAL>>>(whh_f, whh_b, bhh_f, bhh_b);

    fc_kernel<<<TT, 320>>>(fcw, fcb, out);
}